// round 2
// baseline (speedup 1.0000x reference)
#include <cuda_runtime.h>
#include <cuda_bf16.h>

// Problem constants (fixed-shape problem)
#define NB      32
#define NSITES  65536
#define NNGB    13
#define DIM     3
#define NG      48
#define KDIM    (NG * DIM)        // 144
#define NPREP   16                // partial-Wmean blocks fused into transpose grid
#define ROWS_PER_PREP (KDIM / NPREP)  // 9
#define NTILE   (NSITES / 32)     // 2048 transpose tiles

// Scratch (device-global: allocation-free rule)
__device__ float g_InT[NSITES * NB];            // 8 MB, site-major transpose of In
__device__ float g_Wpart[NPREP][DIM * NNGB];    // partial Wmean sums

// ---------------------------------------------------------------------------
// Fused kernel: blocks 0..NPREP-1 compute partial Wmean (overlapped);
// blocks NPREP.. transpose In (NB x NSITES) -> g_InT (NSITES x NB).
//
// Wmean[d][j] = (1/48) * sum_{r : r%3==d} gdiags[r,:] . B[:,j]
//   where B[k][j] = wtVC[k%3][ GnnPerms[k/3][j] ]
// Each prep block p handles rows [p*9, p*9+9): warp w -> row, lanes stride k,
// warp-shuffle reduce, smem-atomic accumulate into 39 slots -> g_Wpart[p].
// ---------------------------------------------------------------------------
__global__ __launch_bounds__(1024)
void fused_prep_transpose(const float* __restrict__ In,
                          const float* __restrict__ wtVC,
                          const float* __restrict__ gdiags,
                          const int*   __restrict__ GnnPerms) {
    if (blockIdx.x >= NPREP) {
        // ---- transpose tile ----
        __shared__ float tile[32][33];
        int s0 = (blockIdx.x - NPREP) * 32;
        int tx = threadIdx.x;   // 0..31
        int ty = threadIdx.y;   // 0..31
        tile[ty][tx] = In[ty * NSITES + s0 + tx];          // coalesced read
        __syncthreads();
        g_InT[(s0 + ty) * NB + tx] = tile[tx][ty];         // coalesced write
    } else {
        // ---- partial Wmean ----
        int p = blockIdx.x;
        __shared__ float B[KDIM][NNGB];     // 144 x 13
        __shared__ float sW[DIM * NNGB];    // 39 accumulators
        int tid = threadIdx.y * 32 + threadIdx.x;

        if (tid < DIM * NNGB) sW[tid] = 0.f;
        for (int i = tid; i < KDIM * NNGB; i += 1024) {
            int k = i / NNGB;
            int j = i % NNGB;
            B[k][j] = wtVC[(k % 3) * NNGB + GnnPerms[(k / 3) * NNGB + j]];
        }
        __syncthreads();

        int w    = tid >> 5;
        int lane = tid & 31;
        if (w < ROWS_PER_PREP) {
            int r = p * ROWS_PER_PREP + w;
            float acc[NNGB];
            #pragma unroll
            for (int j = 0; j < NNGB; j++) acc[j] = 0.f;
            for (int k = lane; k < KDIM; k += 32) {         // coalesced row read
                float gv = gdiags[r * KDIM + k];
                #pragma unroll
                for (int j = 0; j < NNGB; j++) acc[j] += gv * B[k][j];
            }
            #pragma unroll
            for (int j = 0; j < NNGB; j++) {
                #pragma unroll
                for (int off = 16; off > 0; off >>= 1)
                    acc[j] += __shfl_xor_sync(0xffffffffu, acc[j], off);
            }
            if (lane == 0) {
                int d = r % 3;
                #pragma unroll
                for (int j = 0; j < NNGB; j++)
                    atomicAdd(&sW[d * NNGB + j], acc[j]);
            }
        }
        __syncthreads();
        if (tid < DIM * NNGB) g_Wpart[p][tid] = sW[tid];
    }
}

// ---------------------------------------------------------------------------
// Main gather + contraction.
// Block = 32 consecutive sites. Warp w -> site s0+w, lane -> batch b.
// Each gather InT[idx*32 + lane] is one fully-used 128B line per warp.
// Output staged in padded smem, then written coalesced.
// ---------------------------------------------------------------------------
__global__ __launch_bounds__(1024, 2)
void conv_kernel(const int* __restrict__ NNsites, float* __restrict__ out) {
    __shared__ float Wm[40];              // 39 used
    __shared__ int   sidx[NNGB][32];      // indices for 32 sites
    __shared__ float sout[NB][DIM][33];   // lane stride 99 words -> conflict-free

    int tid = threadIdx.x;                // 1024
    int s0  = blockIdx.x * 32;

    if (tid < DIM * NNGB) {
        float s = 0.f;
        #pragma unroll
        for (int p = 0; p < NPREP; p++) s += g_Wpart[p][tid];
        Wm[tid] = s * (1.0f / (float)NG);
    }
    if (tid < NNGB * 32) {
        int j  = tid >> 5;
        int si = tid & 31;
        sidx[j][si] = NNsites[j * NSITES + s0 + si];   // coalesced over si
    }
    __syncthreads();

    int w    = tid >> 5;    // site within block (0..31)
    int lane = tid & 31;    // batch

    float a0 = 0.f, a1 = 0.f, a2 = 0.f;
    #pragma unroll
    for (int j = 0; j < NNGB; j++) {
        int   t = sidx[j][w];                        // broadcast LDS
        float v = g_InT[t * NB + lane];              // coalesced 128B line gather
        a0 += Wm[j]            * v;
        a1 += Wm[NNGB + j]     * v;
        a2 += Wm[2 * NNGB + j] * v;
    }
    sout[lane][0][w] = a0;
    sout[lane][1][w] = a1;
    sout[lane][2][w] = a2;
    __syncthreads();

    // Write out[b][d][s0 + si]: 3072 floats per block, 3 per thread.
    // Within a warp (b,d) fixed, si = lane -> coalesced 128B stores.
    #pragma unroll
    for (int k = 0; k < 3; k++) {
        int idx = tid + k * 1024;
        int b   = idx / 96;
        int r   = idx % 96;
        int d   = r >> 5;
        int si  = r & 31;
        out[(b * DIM + d) * NSITES + s0 + si] = sout[b][d][si];
    }
}

// ---------------------------------------------------------------------------
// Launch: In, wtVC, gdiags, GnnPerms, NNsites (metadata order)
// ---------------------------------------------------------------------------
extern "C" void kernel_launch(void* const* d_in, const int* in_sizes, int n_in,
                              void* d_out, int out_size) {
    const float* In       = (const float*)d_in[0];
    const float* wtVC     = (const float*)d_in[1];
    const float* gdiags   = (const float*)d_in[2];
    const int*   GnnPerms = (const int*)  d_in[3];
    const int*   NNsites  = (const int*)  d_in[4];
    float*       out      = (float*)d_out;

    dim3 tblk(32, 32);
    fused_prep_transpose<<<NTILE + NPREP, tblk>>>(In, wtVC, gdiags, GnnPerms);

    conv_kernel<<<NSITES / 32, 1024>>>(NNsites, out);
}

// round 3
// speedup vs baseline: 1.5614x; 1.5614x over previous
#include <cuda_runtime.h>
#include <cuda_bf16.h>

// Problem constants (fixed-shape problem)
#define NB      32
#define NSITES  65536
#define NNGB    13
#define DIM     3
#define NG      48
#define KDIM    (NG * DIM)             // 144
#define NPREP   16
#define ROWS_PER_PREP (KDIM / NPREP)   // 9

// Scratch (device-global: allocation-free rule)
__device__ __align__(16) float g_InT[NSITES * NB];   // 8 MB, site-major transpose of In
__device__ float g_Wpart[NPREP][DIM * NNGB];
__device__ float g_Wmean[DIM * NNGB];

// ---------------------------------------------------------------------------
// Kernel 1: partial Wmean. 16 blocks x 320 threads; block p handles gdiags
// rows [9p, 9p+9). B[k][j] = wtVC[k%3][GnnPerms[k/3][j]].
// ---------------------------------------------------------------------------
__global__ __launch_bounds__(320)
void prep_kernel(const float* __restrict__ wtVC,
                 const float* __restrict__ gdiags,
                 const int*   __restrict__ GnnPerms) {
    __shared__ float B[KDIM][NNGB];
    __shared__ float sW[DIM * NNGB];
    int tid = threadIdx.x;

    if (tid < DIM * NNGB) sW[tid] = 0.f;
    for (int i = tid; i < KDIM * NNGB; i += 320) {
        int k = i / NNGB, j = i % NNGB;
        B[k][j] = wtVC[(k % 3) * NNGB + GnnPerms[(k / 3) * NNGB + j]];
    }
    __syncthreads();

    int w = tid >> 5, lane = tid & 31;
    if (w < ROWS_PER_PREP) {
        int r = blockIdx.x * ROWS_PER_PREP + w;
        float acc[NNGB];
        #pragma unroll
        for (int j = 0; j < NNGB; j++) acc[j] = 0.f;
        for (int k = lane; k < KDIM; k += 32) {            // coalesced row read
            float gv = gdiags[r * KDIM + k];
            #pragma unroll
            for (int j = 0; j < NNGB; j++) acc[j] += gv * B[k][j];
        }
        #pragma unroll
        for (int j = 0; j < NNGB; j++) {
            #pragma unroll
            for (int off = 16; off > 0; off >>= 1)
                acc[j] += __shfl_xor_sync(0xffffffffu, acc[j], off);
        }
        if (lane == 0) {
            int d = r % 3;
            #pragma unroll
            for (int j = 0; j < NNGB; j++)
                atomicAdd(&sW[d * NNGB + j], acc[j]);
        }
    }
    __syncthreads();
    if (tid < DIM * NNGB) g_Wpart[blockIdx.x][tid] = sW[tid];
}

// ---------------------------------------------------------------------------
// Kernel 2: transpose In (NB x NSITES) -> g_InT (NSITES x NB).
// Block 0 additionally reduces the Wmean partials (prep finished: stream order).
// ---------------------------------------------------------------------------
__global__ void transpose_kernel(const float* __restrict__ In) {
    __shared__ float tile[32][33];
    int tx = threadIdx.x, ty = threadIdx.y;
    int tid = ty * 32 + tx;

    if (blockIdx.x == 0 && tid < DIM * NNGB) {
        float s = 0.f;
        #pragma unroll
        for (int p = 0; p < NPREP; p++) s += g_Wpart[p][tid];
        g_Wmean[tid] = s * (1.0f / (float)NG);
    }

    int s0 = blockIdx.x * 32;
    tile[ty][tx] = In[ty * NSITES + s0 + tx];          // coalesced read
    __syncthreads();
    g_InT[(s0 + ty) * NB + tx] = tile[tx][ty];         // coalesced write
}

// ---------------------------------------------------------------------------
// Kernel 3: main gather + contraction, float4-vectorized.
// Block = 256 threads, 32 sites. Lane l: site = 4*w + (l>>3), float4-col c = l&7
// (batches 4c..4c+3). Each gather is LDG.E.128 covering 4 sites per warp-instr.
// ---------------------------------------------------------------------------
__global__ __launch_bounds__(256, 6)
void conv_kernel(const int* __restrict__ NNsites, float* __restrict__ out) {
    __shared__ float Wm[40];
    __shared__ int   sidx[NNGB][32];
    __shared__ float sout[DIM][NB][33];   // [d][batch][site], pad -> conflict-free

    int tid = threadIdx.x;
    int s0  = blockIdx.x * 32;

    if (tid < DIM * NNGB) Wm[tid] = g_Wmean[tid];
    for (int i = tid; i < NNGB * 32; i += 256) {
        int j = i >> 5, si = i & 31;
        sidx[j][si] = NNsites[j * NSITES + s0 + si];   // coalesced
    }
    __syncthreads();

    int w    = tid >> 5;
    int l    = tid & 31;
    int site = (w << 2) + (l >> 3);   // 0..31
    int c    = l & 7;                 // float4 column -> batches 4c..4c+3

    const float4* __restrict__ InT4 = (const float4*)g_InT;

    float4 a0 = make_float4(0.f, 0.f, 0.f, 0.f);
    float4 a1 = a0, a2 = a0;

    #pragma unroll
    for (int j = 0; j < NNGB; j++) {
        int    t = sidx[j][site];
        float4 v = __ldg(&InT4[t * 8 + c]);      // 128B-line gather
        float w0 = Wm[j], w1 = Wm[NNGB + j], w2 = Wm[2 * NNGB + j];
        a0.x += w0 * v.x; a0.y += w0 * v.y; a0.z += w0 * v.z; a0.w += w0 * v.w;
        a1.x += w1 * v.x; a1.y += w1 * v.y; a1.z += w1 * v.z; a1.w += w1 * v.w;
        a2.x += w2 * v.x; a2.y += w2 * v.y; a2.z += w2 * v.z; a2.w += w2 * v.w;
    }

    // Stage: sout[d][4c+k][site]. Banks (4c+k)*33+site ≡ 4c+4w+r (mod 32): all
    // 32 lanes distinct -> conflict-free scalar STS.
    int b0 = c << 2;
    sout[0][b0 + 0][site] = a0.x; sout[0][b0 + 1][site] = a0.y;
    sout[0][b0 + 2][site] = a0.z; sout[0][b0 + 3][site] = a0.w;
    sout[1][b0 + 0][site] = a1.x; sout[1][b0 + 1][site] = a1.y;
    sout[1][b0 + 2][site] = a1.z; sout[1][b0 + 3][site] = a1.w;
    sout[2][b0 + 0][site] = a2.x; sout[2][b0 + 1][site] = a2.y;
    sout[2][b0 + 2][site] = a2.z; sout[2][b0 + 3][site] = a2.w;
    __syncthreads();

    // Write out[b][d][s0+si]: warp has fixed (b,d), si = lane -> coalesced 128B
    // stores; smem reads consecutive -> conflict-free. 12 floats/thread.
    #pragma unroll
    for (int k = 0; k < 12; k++) {
        int idx  = tid + (k << 8);
        int si   = idx & 31;
        int rest = idx >> 5;         // 0..95
        int d    = rest % 3;
        int b    = rest / 3;
        out[(b * DIM + d) * NSITES + s0 + si] = sout[d][b][si];
    }
}

// ---------------------------------------------------------------------------
// Launch: In, wtVC, gdiags, GnnPerms, NNsites (metadata order)
// ---------------------------------------------------------------------------
extern "C" void kernel_launch(void* const* d_in, const int* in_sizes, int n_in,
                              void* d_out, int out_size) {
    const float* In       = (const float*)d_in[0];
    const float* wtVC     = (const float*)d_in[1];
    const float* gdiags   = (const float*)d_in[2];
    const int*   GnnPerms = (const int*)  d_in[3];
    const int*   NNsites  = (const int*)  d_in[4];
    float*       out      = (float*)d_out;

    prep_kernel<<<NPREP, 320>>>(wtVC, gdiags, GnnPerms);

    dim3 tblk(32, 32);
    transpose_kernel<<<NSITES / 32, tblk>>>(In);

    conv_kernel<<<NSITES / 32, 256>>>(NNsites, out);
}